// round 1
// baseline (speedup 1.0000x reference)
#include <cuda_runtime.h>
#include <cuda_bf16.h>
#include <cstdint>

// ---------------------------------------------------------------------------
// MultiHeadSelfAttention: b=2, s=2048, DIM=HIDDEN=1024, 16 heads, hd=64, fp32
// scores scale = 1024^-5 = 2^-50 (faithful to reference)
// Reference returns (out, attn). We branch on out_size.
// ---------------------------------------------------------------------------

#define SEQ   2048
#define DIMSZ 1024
#define NH    16
#define HD    64
#define MROWS 4096            // b*s
static __device__ __constant__ float kScale = 0x1p-50f;  // 1024^-5 exactly

// Scratch (device globals: no allocation allowed)
__device__ float g_Q[MROWS * DIMSZ];
__device__ float g_K[MROWS * DIMSZ];
__device__ float g_V[MROWS * DIMSZ];
__device__ float g_O[MROWS * DIMSZ];
__device__ float g_M[NH * 2 * SEQ];
__device__ float g_L[NH * 2 * SEQ];

// ---------------------------------------------------------------------------
// C[M,N] = A[M,K] * B[N,K]^T   (Linear layer: y = x @ W.T)
// 64x64 tile, BK=16, 256 threads, 4x4 per thread.
// ---------------------------------------------------------------------------
__global__ __launch_bounds__(256) void gemm_nt_kernel(
    const float* __restrict__ A, const float* __restrict__ B,
    float* __restrict__ C, int M, int N, int K) {
  __shared__ float As[16][64];
  __shared__ float Bs[16][64];
  const int bm = blockIdx.y * 64;
  const int bn = blockIdx.x * 64;
  const int tid = threadIdx.x;
  const int tr = tid >> 4;          // 0..15
  const int tc = tid & 15;          // 0..15
  const int lr = tid >> 2;          // 0..63  (load row)
  const int lc = (tid & 3) * 4;     // 0,4,8,12 (load k-offset)

  float acc[4][4];
#pragma unroll
  for (int i = 0; i < 4; i++)
#pragma unroll
    for (int j = 0; j < 4; j++) acc[i][j] = 0.f;

  const float* Ap = A + (size_t)(bm + lr) * K + lc;
  const float* Bp = B + (size_t)(bn + lr) * K + lc;

  for (int k0 = 0; k0 < K; k0 += 16) {
    float4 a = *(const float4*)(Ap + k0);
    float4 b = *(const float4*)(Bp + k0);
    As[lc + 0][lr] = a.x; As[lc + 1][lr] = a.y;
    As[lc + 2][lr] = a.z; As[lc + 3][lr] = a.w;
    Bs[lc + 0][lr] = b.x; Bs[lc + 1][lr] = b.y;
    Bs[lc + 2][lr] = b.z; Bs[lc + 3][lr] = b.w;
    __syncthreads();
#pragma unroll
    for (int k = 0; k < 16; k++) {
      float4 av = *(const float4*)&As[k][tr * 4];
      float4 bv = *(const float4*)&Bs[k][tc * 4];
      acc[0][0] = fmaf(av.x, bv.x, acc[0][0]);
      acc[0][1] = fmaf(av.x, bv.y, acc[0][1]);
      acc[0][2] = fmaf(av.x, bv.z, acc[0][2]);
      acc[0][3] = fmaf(av.x, bv.w, acc[0][3]);
      acc[1][0] = fmaf(av.y, bv.x, acc[1][0]);
      acc[1][1] = fmaf(av.y, bv.y, acc[1][1]);
      acc[1][2] = fmaf(av.y, bv.z, acc[1][2]);
      acc[1][3] = fmaf(av.y, bv.w, acc[1][3]);
      acc[2][0] = fmaf(av.z, bv.x, acc[2][0]);
      acc[2][1] = fmaf(av.z, bv.y, acc[2][1]);
      acc[2][2] = fmaf(av.z, bv.z, acc[2][2]);
      acc[2][3] = fmaf(av.z, bv.w, acc[2][3]);
      acc[3][0] = fmaf(av.w, bv.x, acc[3][0]);
      acc[3][1] = fmaf(av.w, bv.y, acc[3][1]);
      acc[3][2] = fmaf(av.w, bv.z, acc[3][2]);
      acc[3][3] = fmaf(av.w, bv.w, acc[3][3]);
    }
    __syncthreads();
  }
#pragma unroll
  for (int i = 0; i < 4; i++) {
    float4 o = make_float4(acc[i][0], acc[i][1], acc[i][2], acc[i][3]);
    *(float4*)(C + (size_t)(bm + tr * 4 + i) * N + bn + tc * 4) = o;
  }
}

// ---------------------------------------------------------------------------
// Flash-style attention. One block = 64 query rows for one (h, b).
// KV tiles of 32 rows. Streaming softmax with running (m, l); P reuses the
// K smem buffer. Writes normalized O and final per-row (m, l).
// ---------------------------------------------------------------------------
__global__ __launch_bounds__(256) void flash_attn_kernel(
    const float* __restrict__ Q, const float* __restrict__ K,
    const float* __restrict__ V, const int* __restrict__ mask,
    float* __restrict__ O, float* __restrict__ Mb, float* __restrict__ Lb) {
  __shared__ float Qs[64 * 65];   // [64 rows][64 k], pad 65
  __shared__ float Ks[2112];      // K tile [32][65]; reused as P [64][33]
  __shared__ float Vs[32 * 64];   // [32 rows][64 cols]
  __shared__ int   msk[32];

  const int i0 = blockIdx.x * 64;
  const int h  = blockIdx.y;
  const int b  = blockIdx.z;
  const int tid = threadIdx.x;
  const int tr = tid >> 4;        // 0..15 -> rows tr*4..tr*4+3
  const int tc = tid & 15;        // 0..15 -> S cols tc*2..+1, O cols tc*4..+3

  const float* Qb = Q + (size_t)b * SEQ * DIMSZ + h * HD;
  const float* Kb = K + (size_t)b * SEQ * DIMSZ + h * HD;
  const float* Vb = V + (size_t)b * SEQ * DIMSZ + h * HD;

  // Load Q tile [64][64]
  {
    const int r = tid >> 4;
    const int c4 = (tid & 15) * 4;
#pragma unroll
    for (int p = 0; p < 4; p++) {
      const int rr = p * 16 + r;
      float4 q = *(const float4*)(Qb + (size_t)(i0 + rr) * DIMSZ + c4);
      float* d = Qs + rr * 65 + c4;
      d[0] = q.x; d[1] = q.y; d[2] = q.z; d[3] = q.w;
    }
  }

  float m[4], l[4], Oa[4][4];
#pragma unroll
  for (int i = 0; i < 4; i++) {
    m[i] = -3.0e38f; l[i] = 0.f;
#pragma unroll
    for (int j = 0; j < 4; j++) Oa[i][j] = 0.f;
  }

  for (int j0 = 0; j0 < SEQ; j0 += 32) {
    // Load K, V tile [32][64] + mask
    {
      const int r = tid >> 4;
      const int c4 = (tid & 15) * 4;
#pragma unroll
      for (int p = 0; p < 2; p++) {
        const int rr = p * 16 + r;
        float4 kk = *(const float4*)(Kb + (size_t)(j0 + rr) * DIMSZ + c4);
        float* dk = Ks + rr * 65 + c4;
        dk[0] = kk.x; dk[1] = kk.y; dk[2] = kk.z; dk[3] = kk.w;
        float4 vv = *(const float4*)(Vb + (size_t)(j0 + rr) * DIMSZ + c4);
        float* dv = Vs + rr * 64 + c4;
        dv[0] = vv.x; dv[1] = vv.y; dv[2] = vv.z; dv[3] = vv.w;
      }
      if (tid < 32) msk[tid] = mask[b * SEQ + j0 + tid];
    }
    __syncthreads();

    // S = Q * K^T  (64x32 tile; per-thread 4x2)
    float S[4][2];
#pragma unroll
    for (int i = 0; i < 4; i++) { S[i][0] = 0.f; S[i][1] = 0.f; }
#pragma unroll 8
    for (int k = 0; k < 64; k++) {
      float qa[4], kb2[2];
#pragma unroll
      for (int i = 0; i < 4; i++) qa[i] = Qs[(tr * 4 + i) * 65 + k];
#pragma unroll
      for (int j = 0; j < 2; j++) kb2[j] = Ks[(tc * 2 + j) * 65 + k];
#pragma unroll
      for (int i = 0; i < 4; i++) {
        S[i][0] = fmaf(qa[i], kb2[0], S[i][0]);
        S[i][1] = fmaf(qa[i], kb2[1], S[i][1]);
      }
    }

    // scale + mask + row max
    float mx[4];
#pragma unroll
    for (int i = 0; i < 4; i++) mx[i] = -3.0e38f;
#pragma unroll
    for (int i = 0; i < 4; i++)
#pragma unroll
      for (int j = 0; j < 2; j++) {
        S[i][j] = msk[tc * 2 + j] ? S[i][j] * kScale : -3.0e38f;
        mx[i] = fmaxf(mx[i], S[i][j]);
      }
#pragma unroll
    for (int d = 8; d >= 1; d >>= 1)
#pragma unroll
      for (int i = 0; i < 4; i++)
        mx[i] = fmaxf(mx[i], __shfl_xor_sync(0xffffffffu, mx[i], d));

    __syncthreads();  // all K reads done; Ks about to become P

    float corr[4], rs[4];
#pragma unroll
    for (int i = 0; i < 4; i++) {
      float mn = fmaxf(m[i], mx[i]);
      corr[i] = __expf(m[i] - mn);
      m[i] = mn;
      rs[i] = 0.f;
    }
    float* Ps = Ks;  // [64][33]
#pragma unroll
    for (int i = 0; i < 4; i++)
#pragma unroll
      for (int j = 0; j < 2; j++) {
        float p = __expf(S[i][j] - m[i]);
        rs[i] += p;
        Ps[(tr * 4 + i) * 33 + tc * 2 + j] = p;
      }
#pragma unroll
    for (int d = 8; d >= 1; d >>= 1)
#pragma unroll
      for (int i = 0; i < 4; i++)
        rs[i] += __shfl_xor_sync(0xffffffffu, rs[i], d);
#pragma unroll
    for (int i = 0; i < 4; i++) {
      l[i] = l[i] * corr[i] + rs[i];
#pragma unroll
      for (int j = 0; j < 4; j++) Oa[i][j] *= corr[i];
    }
    __syncthreads();  // P visible

    // O += P * V   (per-thread rows tr*4..+3, cols tc*4..+3)
#pragma unroll 4
    for (int k = 0; k < 32; k++) {
      float pv[4];
#pragma unroll
      for (int i = 0; i < 4; i++) pv[i] = Ps[(tr * 4 + i) * 33 + k];
      float4 v4 = *(const float4*)(Vs + k * 64 + tc * 4);
#pragma unroll
      for (int i = 0; i < 4; i++) {
        Oa[i][0] = fmaf(pv[i], v4.x, Oa[i][0]);
        Oa[i][1] = fmaf(pv[i], v4.y, Oa[i][1]);
        Oa[i][2] = fmaf(pv[i], v4.z, Oa[i][2]);
        Oa[i][3] = fmaf(pv[i], v4.w, Oa[i][3]);
      }
    }
    __syncthreads();  // before next tile overwrites Ks/Vs
  }

  // Finalize: O /= l, write [b, i, h*64 + c]
#pragma unroll
  for (int i = 0; i < 4; i++) {
    float inv = 1.0f / l[i];
    float4 o4 = make_float4(Oa[i][0] * inv, Oa[i][1] * inv,
                            Oa[i][2] * inv, Oa[i][3] * inv);
    *(float4*)(O + (size_t)(b * SEQ + i0 + tr * 4 + i) * DIMSZ + h * HD + tc * 4) = o4;
  }
  if (tc == 0) {
#pragma unroll
    for (int i = 0; i < 4; i++) {
      int gi = i0 + tr * 4 + i;
      Mb[(h * 2 + b) * SEQ + gi] = m[i];
      Lb[(h * 2 + b) * SEQ + gi] = l[i];
    }
  }
}

// ---------------------------------------------------------------------------
// Materialize attn[h,b,i,j] = exp(S*scale - m_i)/l_i (0 where masked).
// One block = 64x64 (i,j) tile for one (h,b).
// ---------------------------------------------------------------------------
__global__ __launch_bounds__(256) void attn_write_kernel(
    const float* __restrict__ Q, const float* __restrict__ K,
    const int* __restrict__ mask, const float* __restrict__ Mb,
    const float* __restrict__ Lb, float* __restrict__ attn) {
  __shared__ float Qs[64 * 65];
  __shared__ float Ks[64 * 65];
  __shared__ int   msk[64];
  const int j0 = blockIdx.x * 64;
  const int i0 = blockIdx.y * 64;
  const int hb = blockIdx.z;          // h*2 + b
  const int h = hb >> 1;
  const int b = hb & 1;
  const int tid = threadIdx.x;
  const int tr = tid >> 4, tc = tid & 15;
  const float* Qb = Q + (size_t)b * SEQ * DIMSZ + h * HD;
  const float* Kb = K + (size_t)b * SEQ * DIMSZ + h * HD;
  {
    const int r = tid >> 4;
    const int c4 = (tid & 15) * 4;
#pragma unroll
    for (int p = 0; p < 4; p++) {
      const int rr = p * 16 + r;
      float4 q = *(const float4*)(Qb + (size_t)(i0 + rr) * DIMSZ + c4);
      float* d = Qs + rr * 65 + c4;
      d[0] = q.x; d[1] = q.y; d[2] = q.z; d[3] = q.w;
      float4 kk = *(const float4*)(Kb + (size_t)(j0 + rr) * DIMSZ + c4);
      float* dk = Ks + rr * 65 + c4;
      dk[0] = kk.x; dk[1] = kk.y; dk[2] = kk.z; dk[3] = kk.w;
    }
    if (tid < 64) msk[tid] = mask[b * SEQ + j0 + tid];
  }
  __syncthreads();

  float S[4][4];
#pragma unroll
  for (int i = 0; i < 4; i++)
#pragma unroll
    for (int j = 0; j < 4; j++) S[i][j] = 0.f;
#pragma unroll 8
  for (int k = 0; k < 64; k++) {
    float qa[4], kb4[4];
#pragma unroll
    for (int i = 0; i < 4; i++) qa[i] = Qs[(tr * 4 + i) * 65 + k];
#pragma unroll
    for (int j = 0; j < 4; j++) kb4[j] = Ks[(tc * 4 + j) * 65 + k];
#pragma unroll
    for (int i = 0; i < 4; i++)
#pragma unroll
      for (int j = 0; j < 4; j++) S[i][j] = fmaf(qa[i], kb4[j], S[i][j]);
  }

  float mrow[4], linv[4];
#pragma unroll
  for (int i = 0; i < 4; i++) {
    int gi = i0 + tr * 4 + i;
    mrow[i] = Mb[hb * SEQ + gi];
    linv[i] = 1.0f / Lb[hb * SEQ + gi];
  }
#pragma unroll
  for (int i = 0; i < 4; i++) {
#pragma unroll
    for (int j = 0; j < 4; j++) {
      float v = msk[tc * 4 + j] ? __expf(S[i][j] * kScale - mrow[i]) * linv[i]
                                : 0.f;
      S[i][j] = v;
    }
    float4 o = make_float4(S[i][0], S[i][1], S[i][2], S[i][3]);
    *(float4*)(attn + ((size_t)hb * SEQ + i0 + tr * 4 + i) * SEQ + j0 + tc * 4) = o;
  }
}

// ---------------------------------------------------------------------------
extern "C" void kernel_launch(void* const* d_in, const int* in_sizes, int n_in,
                              void* d_out, int out_size) {
  const float* x    = (const float*)d_in[0];
  const int*   mask = (const int*)d_in[1];
  const float* Wq   = (const float*)d_in[2];
  const float* Wk   = (const float*)d_in[3];
  const float* Wv   = (const float*)d_in[4];
  const float* Wo   = (const float*)d_in[5];
  float* out = (float*)d_out;

  float *Qp, *Kp, *Vp, *Op, *Mp, *Lp;
  cudaGetSymbolAddress((void**)&Qp, g_Q);
  cudaGetSymbolAddress((void**)&Kp, g_K);
  cudaGetSymbolAddress((void**)&Vp, g_V);
  cudaGetSymbolAddress((void**)&Op, g_O);
  cudaGetSymbolAddress((void**)&Mp, g_M);
  cudaGetSymbolAddress((void**)&Lp, g_L);

  dim3 gb(DIMSZ / 64, MROWS / 64);  // (16, 64)
  gemm_nt_kernel<<<gb, 256>>>(x, Wq, Qp, MROWS, DIMSZ, DIMSZ);
  gemm_nt_kernel<<<gb, 256>>>(x, Wk, Kp, MROWS, DIMSZ, DIMSZ);
  gemm_nt_kernel<<<gb, 256>>>(x, Wv, Vp, MROWS, DIMSZ, DIMSZ);

  flash_attn_kernel<<<dim3(SEQ / 64, NH, 2), 256>>>(Qp, Kp, Vp, mask, Op, Mp, Lp);

  const long long OUT_E = (long long)MROWS * DIMSZ;          // 4194304
  const long long ATTN_E = (long long)NH * 2 * SEQ * SEQ;    // 134217728
  const long long osz = (long long)out_size;

  if (osz >= OUT_E + ATTN_E) {
    gemm_nt_kernel<<<gb, 256>>>(Op, Wo, out, MROWS, DIMSZ, DIMSZ);
    attn_write_kernel<<<dim3(SEQ / 64, SEQ / 64, NH * 2), 256>>>(
        Qp, Kp, mask, Mp, Lp, out + OUT_E);
  } else if (osz == ATTN_E) {
    attn_write_kernel<<<dim3(SEQ / 64, SEQ / 64, NH * 2), 256>>>(
        Qp, Kp, mask, Mp, Lp, out);
  } else {
    gemm_nt_kernel<<<gb, 256>>>(Op, Wo, out, MROWS, DIMSZ, DIMSZ);
  }
}

// round 2
// speedup vs baseline: 26.6635x; 26.6635x over previous
#include <cuda_runtime.h>
#include <cuda_bf16.h>
#include <cstdint>

// ---------------------------------------------------------------------------
// MultiHeadSelfAttention, b=2, s=2048, DIM=HIDDEN=1024, 16 heads, fp32.
// SCALE = 1024^-5 = 2^-50  =>  |scores| < ~3e-14. In fp32, exp(s - max)
// rounds to exactly 1.0f for every unmasked entry (and 0 for masked), so the
// reference softmax is EXACTLY uniform over unmasked positions:
//   attn[h,b,i,j] = mask[b,j] / n[b],   n[b] = sum_j mask[b,j]
//   out[b,i,:]    = ((sum_j mask[b,j]*x[b,j,:]) / n[b]) @ Wv^T @ Wo^T
// independent of i. We compute exactly that.
// ---------------------------------------------------------------------------

#define SEQ   2048
#define DIMSZ 1024
#define NH    16
#define MROWS 4096   // b*s
#define NB    2

__device__ __align__(16) float g_rowpat[NB * SEQ];      // mask[b,j] ? 1/n[b] : 0
__device__ __align__(16) float g_part[NB * 16 * DIMSZ]; // stage-1 partial sums
__device__ __align__(16) float g_xbar[NB * DIMSZ];
__device__ __align__(16) float g_vbar[NB * DIMSZ];
__device__ __align__(16) float g_obar[NB * DIMSZ];

// ---------------------------------------------------------------------------
// 1) Per-batch mask count -> row pattern (deterministic block reduction).
//    grid(NB), block(256)
// ---------------------------------------------------------------------------
__global__ void prep_kernel(const int* __restrict__ mask) {
  __shared__ int red[256];
  __shared__ float s_inv;
  const int b = blockIdx.x;
  const int tid = threadIdx.x;
  int c = 0;
  for (int j = tid; j < SEQ; j += 256) c += (mask[b * SEQ + j] != 0);
  red[tid] = c;
  __syncthreads();
  for (int s = 128; s > 0; s >>= 1) {
    if (tid < s) red[tid] += red[tid + s];
    __syncthreads();
  }
  if (tid == 0) s_inv = 1.0f / (float)red[0];
  __syncthreads();
  const float inv = s_inv;
  for (int j = tid; j < SEQ; j += 256)
    g_rowpat[b * SEQ + j] = (mask[b * SEQ + j] != 0) ? inv : 0.0f;
}

// ---------------------------------------------------------------------------
// 2a) Stage-1 weighted column sums: 128 j-rows per block.
//     grid(DIMSZ/256, 16, NB), block(256)
// ---------------------------------------------------------------------------
__global__ __launch_bounds__(256) void xbar1_kernel(const float* __restrict__ x) {
  const int d = blockIdx.x * 256 + threadIdx.x;
  const int chunk = blockIdx.y;          // 0..15
  const int b = blockIdx.z;
  const int j0 = chunk * 128;
  float s = 0.f;
  const float* xp = x + ((size_t)b * SEQ + j0) * DIMSZ + d;
  const float* wp = g_rowpat + b * SEQ + j0;
#pragma unroll 4
  for (int j = 0; j < 128; j++)
    s = fmaf(wp[j], xp[(size_t)j * DIMSZ], s);
  g_part[((b * 16) + chunk) * DIMSZ + d] = s;
}

// 2b) Stage-2: sum 16 partials.  grid(DIMSZ/256, NB), block(256)
__global__ void xbar2_kernel() {
  const int d = blockIdx.x * 256 + threadIdx.x;
  const int b = blockIdx.y;
  float s = 0.f;
#pragma unroll
  for (int c = 0; c < 16; c++) s += g_part[((b * 16) + c) * DIMSZ + d];
  g_xbar[b * DIMSZ + d] = s;
}

// ---------------------------------------------------------------------------
// 3) GEMV: outv[b][o] = sum_d in[b][d] * W[o][d]. One warp per output.
//    grid(DIMSZ/8, NB), block(256)
// ---------------------------------------------------------------------------
__global__ __launch_bounds__(256) void gemv_kernel(
    const float* __restrict__ W, const float* __restrict__ in,
    float* __restrict__ outv) {
  const int b = blockIdx.y;
  const int warp = threadIdx.x >> 5;
  const int lane = threadIdx.x & 31;
  const int o = blockIdx.x * 8 + warp;
  const float4* wp = (const float4*)(W + (size_t)o * DIMSZ);
  const float4* vp = (const float4*)(in + b * DIMSZ);
  float acc = 0.f;
#pragma unroll
  for (int it = 0; it < DIMSZ / 128; it++) {   // 8 iters
    float4 w = wp[it * 32 + lane];
    float4 v = __ldg(&vp[it * 32 + lane]);
    acc = fmaf(w.x, v.x, acc);
    acc = fmaf(w.y, v.y, acc);
    acc = fmaf(w.z, v.z, acc);
    acc = fmaf(w.w, v.w, acc);
  }
#pragma unroll
  for (int d = 16; d >= 1; d >>= 1) acc += __shfl_xor_sync(0xffffffffu, acc, d);
  if (lane == 0) outv[b * DIMSZ + o] = acc;
}

// ---------------------------------------------------------------------------
// 4) Broadcast obar to all sequence rows.  grid(MROWS), block(256)
// ---------------------------------------------------------------------------
__global__ void bcast_out_kernel(float* __restrict__ out) {
  const int row = blockIdx.x;
  const int b = row >> 11;
  const float4* src = (const float4*)(g_obar + b * DIMSZ);
  float4* dst = (float4*)(out + (size_t)row * DIMSZ);
  dst[threadIdx.x] = __ldg(&src[threadIdx.x]);
}

// ---------------------------------------------------------------------------
// 5) attn[h,b,i,j] = g_rowpat[b][j]. 65536 rows of 512 float4.
//    grid(NH*NB*SEQ), block(512). Streaming stores (bypass L2 persistence).
// ---------------------------------------------------------------------------
__global__ __launch_bounds__(512) void attn_fill_kernel(float* __restrict__ attn) {
  const int row = blockIdx.x;                 // [h][b][i] flattened
  const int b = (row >> 11) & 1;
  const float4* src = (const float4*)(g_rowpat + b * SEQ);
  float4* dst = (float4*)(attn + (size_t)row * SEQ);
  float4 v = __ldg(&src[threadIdx.x]);
  __stcs(&dst[threadIdx.x], v);
}

// ---------------------------------------------------------------------------
extern "C" void kernel_launch(void* const* d_in, const int* in_sizes, int n_in,
                              void* d_out, int out_size) {
  const float* x    = (const float*)d_in[0];
  const int*   mask = (const int*)d_in[1];
  // d_in[2]=Wq, d_in[3]=Wk unused: softmax is exactly uniform at scale 2^-50.
  const float* Wv   = (const float*)d_in[4];
  const float* Wo   = (const float*)d_in[5];
  float* out = (float*)d_out;

  float *vbarp, *obarp, *xbarp;
  cudaGetSymbolAddress((void**)&xbarp, g_xbar);
  cudaGetSymbolAddress((void**)&vbarp, g_vbar);
  cudaGetSymbolAddress((void**)&obarp, g_obar);

  const long long OUT_E = (long long)MROWS * DIMSZ;        // 4194304
  const long long ATTN_E = (long long)NH * NB * SEQ * SEQ; // 134217728
  const long long osz = (long long)out_size;
  const bool want_out = (osz != ATTN_E);
  const bool want_attn = (osz >= ATTN_E);
  float* attn_ptr = (osz >= OUT_E + ATTN_E) ? out + OUT_E : out;

  prep_kernel<<<NB, 256>>>(mask);

  if (want_out) {
    xbar1_kernel<<<dim3(DIMSZ / 256, 16, NB), 256>>>(x);
    xbar2_kernel<<<dim3(DIMSZ / 256, NB), 256>>>();
    gemv_kernel<<<dim3(DIMSZ / 8, NB), 256>>>(Wv, xbarp, vbarp);
    gemv_kernel<<<dim3(DIMSZ / 8, NB), 256>>>(Wo, vbarp, obarp);
    bcast_out_kernel<<<MROWS, 256>>>(out);
  }
  if (want_attn) {
    attn_fill_kernel<<<NH * NB * SEQ, 512>>>(attn_ptr);
  }
}

// round 4
// speedup vs baseline: 32.2372x; 1.2090x over previous
#include <cuda_runtime.h>
#include <cuda_bf16.h>
#include <cstdint>

// ---------------------------------------------------------------------------
// MultiHeadSelfAttention, b=2, s=2048, DIM=HIDDEN=1024, 16 heads, fp32.
// SCALE = 1024^-5 = 2^-50  =>  |scores| < ~3e-14. In fp32, exp(s - max)
// rounds to exactly 1.0f for every unmasked entry (and 0 for masked), so the
// reference softmax is EXACTLY uniform over unmasked positions:
//   attn[h,b,i,j] = mask[b,j] / n[b],   n[b] = sum_j mask[b,j]
//   out[b,i,:]    = ((sum_j mask[b,j]*x[b,j,:]) / n[b]) @ Wv^T @ Wo^T
// independent of i. We compute exactly that.
// ---------------------------------------------------------------------------

#define SEQ   2048
#define DIMSZ 1024
#define NH    16
#define MROWS 4096   // b*s
#define NB    2
#define NCHUNK 32    // xbar stage-1 chunks per batch

__device__ __align__(16) float g_rowpat[NB * SEQ];          // mask ? 1/n : 0
__device__ __align__(16) float g_part[NB * NCHUNK * DIMSZ]; // stage-1 partials
__device__ __align__(16) float g_xbar[NB * DIMSZ];
__device__ __align__(16) float g_vbar[NB * DIMSZ];
__device__ __align__(16) float g_obar[NB * DIMSZ];

// Side stream + events for fork/join overlap inside graph capture.
// Created once at load time (host-side API; no device memory allocation).
struct StreamHolder {
  cudaStream_t s = nullptr;
  cudaEvent_t e_fork = nullptr, e_join = nullptr;
  bool ok = false;
  StreamHolder() {
    ok = (cudaStreamCreateWithFlags(&s, cudaStreamNonBlocking) == cudaSuccess) &&
         (cudaEventCreateWithFlags(&e_fork, cudaEventDisableTiming) == cudaSuccess) &&
         (cudaEventCreateWithFlags(&e_join, cudaEventDisableTiming) == cudaSuccess);
  }
};
static StreamHolder g_sh;

// ---------------------------------------------------------------------------
// 1) Per-batch mask count -> row pattern.  grid(NB), block(256)
// ---------------------------------------------------------------------------
__global__ void prep_kernel(const int* __restrict__ mask) {
  __shared__ int red[256];
  __shared__ float s_inv;
  const int b = blockIdx.x;
  const int tid = threadIdx.x;
  int c = 0;
  for (int j = tid; j < SEQ; j += 256) c += (mask[b * SEQ + j] != 0);
  red[tid] = c;
  __syncthreads();
  for (int s = 128; s > 0; s >>= 1) {
    if (tid < s) red[tid] += red[tid + s];
    __syncthreads();
  }
  if (tid == 0) s_inv = 1.0f / (float)red[0];
  __syncthreads();
  const float inv = s_inv;
  for (int j = tid; j < SEQ; j += 256)
    g_rowpat[b * SEQ + j] = (mask[b * SEQ + j] != 0) ? inv : 0.0f;
}

// ---------------------------------------------------------------------------
// 2a) Stage-1 weighted column sums: 64 j-rows per block.
//     grid(DIMSZ/256, NCHUNK, NB), block(256)
// ---------------------------------------------------------------------------
__global__ __launch_bounds__(256) void xbar1_kernel(const float* __restrict__ x) {
  const int d = blockIdx.x * 256 + threadIdx.x;
  const int chunk = blockIdx.y;
  const int b = blockIdx.z;
  const int j0 = chunk * (SEQ / NCHUNK);      // 64 rows
  float s = 0.f;
  const float* xp = x + ((size_t)b * SEQ + j0) * DIMSZ + d;
  const float* wp = g_rowpat + b * SEQ + j0;
#pragma unroll 8
  for (int j = 0; j < SEQ / NCHUNK; j++)
    s = fmaf(wp[j], xp[(size_t)j * DIMSZ], s);
  g_part[((b * NCHUNK) + chunk) * DIMSZ + d] = s;
}

// 2b) Stage-2: sum NCHUNK partials.  grid(DIMSZ/256, NB), block(256)
__global__ void xbar2_kernel() {
  const int d = blockIdx.x * 256 + threadIdx.x;
  const int b = blockIdx.y;
  float s = 0.f;
#pragma unroll
  for (int c = 0; c < NCHUNK; c++) s += g_part[((b * NCHUNK) + c) * DIMSZ + d];
  g_xbar[b * DIMSZ + d] = s;
}

// ---------------------------------------------------------------------------
// 3) GEMV: outv[b][o] = sum_d in[b][d] * W[o][d].
//    Block 256 = 8 warps; 4 outputs/block, 2 warps/output (K split in half).
//    grid(DIMSZ/4, NB)
// ---------------------------------------------------------------------------
__global__ __launch_bounds__(256) void gemv_kernel(
    const float* __restrict__ W, const float* __restrict__ in,
    float* __restrict__ outv) {
  __shared__ float part[8];
  const int b = blockIdx.y;
  const int warp = threadIdx.x >> 5;
  const int lane = threadIdx.x & 31;
  const int o = blockIdx.x * 4 + (warp >> 1);
  const int half = warp & 1;
  const float4* wp = (const float4*)(W + (size_t)o * DIMSZ) + half * 128;
  const float4* vp = (const float4*)(in + b * DIMSZ) + half * 128;
  float acc = 0.f;
#pragma unroll
  for (int it = 0; it < 4; it++) {
    float4 w = wp[it * 32 + lane];
    float4 v = __ldg(&vp[it * 32 + lane]);
    acc = fmaf(w.x, v.x, acc);
    acc = fmaf(w.y, v.y, acc);
    acc = fmaf(w.z, v.z, acc);
    acc = fmaf(w.w, v.w, acc);
  }
#pragma unroll
  for (int d = 16; d >= 1; d >>= 1) acc += __shfl_xor_sync(0xffffffffu, acc, d);
  if (lane == 0) part[warp] = acc;
  __syncthreads();
  if (threadIdx.x < 4)
    outv[b * DIMSZ + blockIdx.x * 4 + threadIdx.x] =
        part[2 * threadIdx.x] + part[2 * threadIdx.x + 1];
}

// ---------------------------------------------------------------------------
// 4) Broadcast obar to all sequence rows.  grid(MROWS/8), block(512):
//    each block writes 8 rows from registers.
// ---------------------------------------------------------------------------
__global__ __launch_bounds__(512) void bcast_out_kernel(float* __restrict__ out) {
  const int r0 = blockIdx.x * 8;
  const int b = r0 >> 11;                       // 8 rows never straddle b
  float4 v = __ldg((const float4*)(g_obar + b * DIMSZ) + (threadIdx.x >> 1));
  // 512 threads, 256 float4 per row: two threads per float4? No — use 256 f4.
  // Simpler: threadIdx.x < 256 handles row data; rest idle would waste.
  // Instead: each thread owns float4 index (threadIdx.x & 255), rows split 2-way.
  const int f4 = threadIdx.x & 255;
  const int rh = threadIdx.x >> 8;              // 0 or 1: row parity
  v = __ldg((const float4*)(g_obar + b * DIMSZ) + f4);
  float4* dst = (float4*)(out + (size_t)r0 * DIMSZ) + rh * (DIMSZ / 4) + f4;
#pragma unroll
  for (int r = 0; r < 4; r++)
    __stcs(dst + r * 2 * (DIMSZ / 4), v);
}

// ---------------------------------------------------------------------------
// 5) attn fill: one block = fixed (h,b), 16 consecutive i rows, value from
//    registers (L2 read traffic: 32 MB total instead of 512 MB).
//    grid(NH*NB*(SEQ/16)) = 4096, block(512)
// ---------------------------------------------------------------------------
__global__ __launch_bounds__(512) void attn_fill_kernel(float* __restrict__ attn) {
  const int blk = blockIdx.x;
  const int ichunk = blk & 127;       // SEQ/16 = 128
  const int hb = blk >> 7;            // h*2 + b
  const int b = hb & 1;
  float4 v = __ldg((const float4*)(g_rowpat + b * SEQ) + threadIdx.x);
  float4* dst = (float4*)(attn + ((size_t)hb * SEQ + ichunk * 16) * SEQ) + threadIdx.x;
#pragma unroll
  for (int r = 0; r < 16; r++)
    __stcs(dst + (size_t)r * (SEQ / 4), v);
}

// ---------------------------------------------------------------------------
static void launch_out_chain(const float* x, const float* Wv, const float* Wo,
                             float* out, float* xbarp, float* vbarp,
                             float* obarp, cudaStream_t st) {
  xbar1_kernel<<<dim3(DIMSZ / 256, NCHUNK, NB), 256, 0, st>>>(x);
  xbar2_kernel<<<dim3(DIMSZ / 256, NB), 256, 0, st>>>();
  gemv_kernel<<<dim3(DIMSZ / 4, NB), 256, 0, st>>>(Wv, xbarp, vbarp);
  gemv_kernel<<<dim3(DIMSZ / 4, NB), 256, 0, st>>>(Wo, vbarp, obarp);
  bcast_out_kernel<<<MROWS / 8, 512, 0, st>>>(out);
}

extern "C" void kernel_launch(void* const* d_in, const int* in_sizes, int n_in,
                              void* d_out, int out_size) {
  const float* x    = (const float*)d_in[0];
  const int*   mask = (const int*)d_in[1];
  // d_in[2]=Wq, d_in[3]=Wk unused: softmax is exactly uniform at scale 2^-50.
  const float* Wv   = (const float*)d_in[4];
  const float* Wo   = (const float*)d_in[5];
  float* out = (float*)d_out;

  float *vbarp, *obarp, *xbarp;
  cudaGetSymbolAddress((void**)&xbarp, g_xbar);
  cudaGetSymbolAddress((void**)&vbarp, g_vbar);
  cudaGetSymbolAddress((void**)&obarp, g_obar);

  const long long OUT_E = (long long)MROWS * DIMSZ;        // 4194304
  const long long ATTN_E = (long long)NH * NB * SEQ * SEQ; // 134217728
  const long long osz = (long long)out_size;
  const bool want_out = (osz != ATTN_E);
  const bool want_attn = (osz >= ATTN_E);
  float* attn_ptr = (osz >= OUT_E + ATTN_E) ? out + OUT_E : out;

  prep_kernel<<<NB, 256>>>(mask);

  if (want_out && want_attn && g_sh.ok) {
    // Fork: out-chain on side stream, bulk attn fill on the capture stream.
    cudaEventRecord(g_sh.e_fork, 0);
    cudaStreamWaitEvent(g_sh.s, g_sh.e_fork, 0);
    launch_out_chain(x, Wv, Wo, out, xbarp, vbarp, obarp, g_sh.s);
    attn_fill_kernel<<<NH * NB * (SEQ / 16), 512>>>(attn_ptr);
    cudaEventRecord(g_sh.e_join, g_sh.s);
    cudaStreamWaitEvent(0, g_sh.e_join, 0);
  } else {
    if (want_out)
      launch_out_chain(x, Wv, Wo, out, xbarp, vbarp, obarp, 0);
    if (want_attn)
      attn_fill_kernel<<<NH * NB * (SEQ / 16), 512>>>(attn_ptr);
  }
}